// round 1
// baseline (speedup 1.0000x reference)
#include <cuda_runtime.h>
#include <math.h>

#define NN   50000
#define EE   800000
#define HIDD 128
#define FEE  16
#define BBB  8
#define NEG_SLOPE 0.2f

// ---------------- scratch (static device memory; no allocations) ----------------
__device__ float g_xl[NN * HIDD];
__device__ float g_xr[NN * HIDD];
__device__ float g_h [NN * HIDD];
__device__ float g_h2[NN * HIDD];
__device__ int   g_deg[NN];
__device__ int   g_off[NN + 1];
__device__ int   g_cur[NN];
__device__ int   g_src[EE];
__device__ float g_eattr[EE * FEE];
__device__ float    g_psum[2 * BBB * HIDD];
__device__ unsigned g_pmax[2 * BBB * HIDD];
__device__ int      g_pcnt[2 * BBB];

// ---------------- helpers ----------------
__device__ __forceinline__ unsigned enc_ord(float f) {
    unsigned u = __float_as_uint(f);
    return (u & 0x80000000u) ? ~u : (u | 0x80000000u);
}
__device__ __forceinline__ float dec_ord(unsigned e) {
    return (e & 0x80000000u) ? __uint_as_float(e ^ 0x80000000u) : __uint_as_float(~e);
}

// ---------------- CSR build ----------------
__global__ void count_kernel(const int* __restrict__ ei, int* __restrict__ deg, int E) {
    int e = blockIdx.x * blockDim.x + threadIdx.x;
    if (e >= E) return;
    atomicAdd(&deg[ei[E + e]], 1);
}

__global__ void scan_kernel(const int* __restrict__ deg, int* __restrict__ off,
                            int* __restrict__ cur, int n) {
    __shared__ int sh[1024];
    __shared__ int carry_s;
    int tid = threadIdx.x;
    if (tid == 0) carry_s = 0;
    __syncthreads();
    for (int base = 0; base < n; base += 1024) {
        int idx = base + tid;
        int v = (idx < n) ? deg[idx] : 0;
        sh[tid] = v;
        __syncthreads();
        for (int o = 1; o < 1024; o <<= 1) {
            int t = (tid >= o) ? sh[tid - o] : 0;
            __syncthreads();
            sh[tid] += t;
            __syncthreads();
        }
        int excl = carry_s + sh[tid] - v;
        if (idx < n) { off[idx] = excl; cur[idx] = excl; }
        __syncthreads();
        if (tid == 0) carry_s += sh[1023];
        __syncthreads();
    }
    if (tid == 0) off[n] = carry_s;
}

__global__ void scatter_kernel(const int* __restrict__ ei, const float* __restrict__ eattr_in,
                               int* __restrict__ cur, int* __restrict__ csr_src,
                               float* __restrict__ eattr_out, int E) {
    int e = blockIdx.x * blockDim.x + threadIdx.x;
    if (e >= E) return;
    int src = ei[e];
    int dst = ei[E + e];
    int pos = atomicAdd(&cur[dst], 1);
    csr_src[pos] = src;
    const float4* s = (const float4*)&eattr_in[(size_t)e * FEE];
    float4* d = (float4*)&eattr_out[(size_t)pos * FEE];
    d[0] = s[0]; d[1] = s[1]; d[2] = s[2]; d[3] = s[3];
}

// ---------------- node GEMM: out[n,128] = A[n,128] @ W[128,128] + b ----------------
// grid (2, ceil(n/128)), 128 threads, 8x8 micro-tile per thread.
__global__ __launch_bounds__(128) void gemm_kernel(
    const float* __restrict__ A, const float* __restrict__ W,
    const float* __restrict__ bias, float* __restrict__ out, int nrows)
{
    __shared__ float As[16][132];   // [k][row] transposed, padded
    __shared__ float Bs[16][64];    // [k][col]
    int tid  = threadIdx.x;
    int row0 = blockIdx.y * 128;
    int col0 = blockIdx.x * 64;
    int tr = tid & 15;      // 0..15 -> rows {tr*4..+3, 64+tr*4..+3}
    int tc = tid >> 4;      // 0..7  -> cols {tc*4..+3, 32+tc*4..+3}

    float acc[8][8];
#pragma unroll
    for (int i = 0; i < 8; i++)
#pragma unroll
        for (int j = 0; j < 8; j++) acc[i][j] = 0.f;

    for (int k0 = 0; k0 < 128; k0 += 16) {
        // A chunk -> transposed shared
#pragma unroll
        for (int i = 0; i < 4; i++) {
            int r = (tid >> 2) + 32 * i;
            int kq = (tid & 3) * 4;
            int grow = row0 + r;
            float4 a = (grow < nrows) ? *(const float4*)&A[(size_t)grow * 128 + k0 + kq]
                                      : make_float4(0.f, 0.f, 0.f, 0.f);
            As[kq + 0][r] = a.x; As[kq + 1][r] = a.y;
            As[kq + 2][r] = a.z; As[kq + 3][r] = a.w;
        }
        // B chunk
#pragma unroll
        for (int i = 0; i < 2; i++) {
            int t = tid + i * 128;
            int k = t >> 4;
            int cq = (t & 15) * 4;
            *(float4*)&Bs[k][cq] = *(const float4*)&W[(size_t)(k0 + k) * 128 + col0 + cq];
        }
        __syncthreads();
#pragma unroll
        for (int k = 0; k < 16; k++) {
            float4 a0 = *(const float4*)&As[k][tr * 4];
            float4 a1 = *(const float4*)&As[k][64 + tr * 4];
            float4 b0 = *(const float4*)&Bs[k][tc * 4];
            float4 b1 = *(const float4*)&Bs[k][32 + tc * 4];
            float ar[8] = {a0.x, a0.y, a0.z, a0.w, a1.x, a1.y, a1.z, a1.w};
            float bc[8] = {b0.x, b0.y, b0.z, b0.w, b1.x, b1.y, b1.z, b1.w};
#pragma unroll
            for (int i = 0; i < 8; i++)
#pragma unroll
                for (int j = 0; j < 8; j++) acc[i][j] += ar[i] * bc[j];
        }
        __syncthreads();
    }
    float4 bA = *(const float4*)&bias[col0 + tc * 4];
    float4 bB = *(const float4*)&bias[col0 + 32 + tc * 4];
#pragma unroll
    for (int i = 0; i < 8; i++) {
        int grow = row0 + ((i < 4) ? (tr * 4 + i) : (64 + tr * 4 + i - 4));
        if (grow >= nrows) continue;
        float4 o0 = make_float4(acc[i][0] + bA.x, acc[i][1] + bA.y,
                                acc[i][2] + bA.z, acc[i][3] + bA.w);
        float4 o1 = make_float4(acc[i][4] + bB.x, acc[i][5] + bB.y,
                                acc[i][6] + bB.z, acc[i][7] + bB.w);
        *(float4*)&out[(size_t)grow * 128 + col0 + tc * 4]      = o0;
        *(float4*)&out[(size_t)grow * 128 + col0 + 32 + tc * 4] = o1;
    }
}

// ---------------- fused GATv2 edge pass (one warp per destination node) ----------------
__global__ __launch_bounds__(256) void edge_kernel(
    const float* __restrict__ xl, const float* __restrict__ xr,
    const float* __restrict__ eattr, const int* __restrict__ csr_src,
    const int* __restrict__ off, const float* __restrict__ We,
    const float* __restrict__ att, const float* __restrict__ bias,
    float* __restrict__ out, int n_nodes)
{
    int warp = (blockIdx.x * blockDim.x + threadIdx.x) >> 5;
    int lane = threadIdx.x & 31;
    if (warp >= n_nodes) return;
    // lane -> head = lane/8, channels ch..ch+3 (float4) within that head
    int ch = ((lane >> 3) << 5) + ((lane & 7) << 2);

    float4 Wreg[16];
#pragma unroll
    for (int k = 0; k < 16; k++) Wreg[k] = *(const float4*)&We[k * 128 + ch];
    float4 att4 = *(const float4*)&att[ch];
    float4 xr4  = *(const float4*)&xr[(size_t)warp * 128 + ch];

    float4 acc = make_float4(0.f, 0.f, 0.f, 0.f);
    float denom = 0.f;
    int s = off[warp], e = off[warp + 1];

    for (int i = s; i < e; i++) {
        int src = __ldg(&csr_src[i]);
        float4 xl4 = *(const float4*)&xl[(size_t)src * 128 + ch];
        float4 m = make_float4(xl4.x + xr4.x, xl4.y + xr4.y,
                               xl4.z + xr4.z, xl4.w + xr4.w);
#pragma unroll
        for (int kk = 0; kk < 4; kk++) {
            float4 ea = *(const float4*)&eattr[(size_t)i * FEE + kk * 4];
            m.x += ea.x * Wreg[4 * kk + 0].x + ea.y * Wreg[4 * kk + 1].x
                 + ea.z * Wreg[4 * kk + 2].x + ea.w * Wreg[4 * kk + 3].x;
            m.y += ea.x * Wreg[4 * kk + 0].y + ea.y * Wreg[4 * kk + 1].y
                 + ea.z * Wreg[4 * kk + 2].y + ea.w * Wreg[4 * kk + 3].y;
            m.z += ea.x * Wreg[4 * kk + 0].z + ea.y * Wreg[4 * kk + 1].z
                 + ea.z * Wreg[4 * kk + 2].z + ea.w * Wreg[4 * kk + 3].z;
            m.w += ea.x * Wreg[4 * kk + 0].w + ea.y * Wreg[4 * kk + 1].w
                 + ea.z * Wreg[4 * kk + 2].w + ea.w * Wreg[4 * kk + 3].w;
        }
        float lx = (m.x > 0.f) ? m.x : NEG_SLOPE * m.x;
        float ly = (m.y > 0.f) ? m.y : NEG_SLOPE * m.y;
        float lz = (m.z > 0.f) ? m.z : NEG_SLOPE * m.z;
        float lw = (m.w > 0.f) ? m.w : NEG_SLOPE * m.w;
        float p = lx * att4.x + ly * att4.y + lz * att4.z + lw * att4.w;
        p += __shfl_xor_sync(0xffffffffu, p, 1);
        p += __shfl_xor_sync(0xffffffffu, p, 2);
        p += __shfl_xor_sync(0xffffffffu, p, 4);
        float ex = __expf(p);
        denom += ex;
        acc.x += ex * xl4.x; acc.y += ex * xl4.y;
        acc.z += ex * xl4.z; acc.w += ex * xl4.w;
    }
    float inv = 1.f / (denom + 1e-16f);
    float4 b4 = *(const float4*)&bias[ch];
    float ox = acc.x * inv + b4.x;
    float oy = acc.y * inv + b4.y;
    float oz = acc.z * inv + b4.z;
    float ow = acc.w * inv + b4.w;
    float4 o;
    o.x = (ox > 0.f) ? ox : expm1f(ox);
    o.y = (oy > 0.f) ? oy : expm1f(oy);
    o.z = (oz > 0.f) ? oz : expm1f(oz);
    o.w = (ow > 0.f) ? ow : expm1f(ow);
    *(float4*)&out[(size_t)warp * 128 + ch] = o;
}

// ---------------- batch pooling (mean + max per batch segment) ----------------
__global__ __launch_bounds__(128) void pool_kernel(
    const float* __restrict__ h, const int* __restrict__ batch,
    float* __restrict__ gsum, unsigned* __restrict__ gmax, int* __restrict__ gcnt,
    int n_nodes)
{
    __shared__ float    ssum[BBB][HIDD];
    __shared__ unsigned smax[BBB][HIDD];
    __shared__ int      scnt[BBB];
    int tid = threadIdx.x;
#pragma unroll
    for (int b = 0; b < BBB; b++) { ssum[b][tid] = 0.f; smax[b][tid] = 0u; }
    if (tid < BBB) scnt[tid] = 0;
    __syncthreads();
    int chunk = (n_nodes + gridDim.x - 1) / gridDim.x;
    int st = blockIdx.x * chunk;
    int en = min(st + chunk, n_nodes);
    for (int n = st; n < en; n++) {
        int b = __ldg(&batch[n]);
        float v = h[(size_t)n * 128 + tid];
        ssum[b][tid] += v;
        unsigned ev = enc_ord(v);
        if (ev > smax[b][tid]) smax[b][tid] = ev;
        if (tid == 0) scnt[b]++;
    }
    __syncthreads();
#pragma unroll
    for (int b = 0; b < BBB; b++) {
        atomicAdd(&gsum[b * HIDD + tid], ssum[b][tid]);
        atomicMax(&gmax[b * HIDD + tid], smax[b][tid]);
    }
    if (tid < BBB) atomicAdd(&gcnt[tid], scnt[tid]);
}

// ---------------- FC head ----------------
__global__ __launch_bounds__(128) void fc_kernel(
    const float* __restrict__ gsum, const unsigned* __restrict__ gmax,
    const int* __restrict__ gcnt,
    const float* __restrict__ Wf1, const float* __restrict__ bf1,
    const float* __restrict__ Wf2, const float* __restrict__ bf2,
    float* __restrict__ out)
{
    __shared__ float comb[512];
    __shared__ float hid[128];
    int tid = threadIdx.x;
    for (int b = 0; b < BBB; b++) {
#pragma unroll
        for (int g = 0; g < 2; g++) {
            int cnt = gcnt[g * BBB + b];
            float invc = 1.f / (float)max(cnt, 1);
            float mean = gsum[(size_t)(g * BBB + b) * HIDD + tid] * invc;
            unsigned mu = gmax[(size_t)(g * BBB + b) * HIDD + tid];
            float mx = (cnt > 0) ? dec_ord(mu) : 0.f;
            comb[g * 256 + tid]       = mean;
            comb[g * 256 + 128 + tid] = mx;
        }
        __syncthreads();
        float a = bf1[tid];
        for (int i = 0; i < 512; i++) a += comb[i] * Wf1[(size_t)i * 128 + tid];
        hid[tid] = fmaxf(a, 0.f);
        __syncthreads();
        if (tid < 32) {
            float s = 0.f;
            for (int j = tid; j < 128; j += 32) s += hid[j] * Wf2[j];
            s += __shfl_xor_sync(0xffffffffu, s, 1);
            s += __shfl_xor_sync(0xffffffffu, s, 2);
            s += __shfl_xor_sync(0xffffffffu, s, 4);
            s += __shfl_xor_sync(0xffffffffu, s, 8);
            s += __shfl_xor_sync(0xffffffffu, s, 16);
            if (tid == 0) out[b] = 1.f / (1.f + __expf(-(s + bf2[0])));
        }
        __syncthreads();
    }
}

// ---------------- launch ----------------
extern "C" void kernel_launch(void* const* d_in, const int* in_sizes, int n_in,
                              void* d_out, int out_size)
{
    (void)n_in; (void)out_size;
    int n = in_sizes[3];          // nodes
    int E = in_sizes[1] / 2;      // edges

    float *xl, *xr, *h, *h2, *eattr, *psum;
    int *deg, *off, *cur, *src, *pcnt;
    unsigned *pmax;
    void* p;
    cudaGetSymbolAddress(&p, g_xl);    xl    = (float*)p;
    cudaGetSymbolAddress(&p, g_xr);    xr    = (float*)p;
    cudaGetSymbolAddress(&p, g_h);     h     = (float*)p;
    cudaGetSymbolAddress(&p, g_h2);    h2    = (float*)p;
    cudaGetSymbolAddress(&p, g_deg);   deg   = (int*)p;
    cudaGetSymbolAddress(&p, g_off);   off   = (int*)p;
    cudaGetSymbolAddress(&p, g_cur);   cur   = (int*)p;
    cudaGetSymbolAddress(&p, g_src);   src   = (int*)p;
    cudaGetSymbolAddress(&p, g_eattr); eattr = (float*)p;
    cudaGetSymbolAddress(&p, g_psum);  psum  = (float*)p;
    cudaGetSymbolAddress(&p, g_pmax);  pmax  = (unsigned*)p;
    cudaGetSymbolAddress(&p, g_pcnt);  pcnt  = (int*)p;

    const float* W1l  = (const float*)d_in[8];
    const float* b1l  = (const float*)d_in[9];
    const float* W1r  = (const float*)d_in[10];
    const float* b1r  = (const float*)d_in[11];
    const float* W1e  = (const float*)d_in[12];
    const float* att1 = (const float*)d_in[13];
    const float* bias1= (const float*)d_in[14];
    const float* W2l  = (const float*)d_in[15];
    const float* b2l  = (const float*)d_in[16];
    const float* W2r  = (const float*)d_in[17];
    const float* b2r  = (const float*)d_in[18];
    const float* W2e  = (const float*)d_in[19];
    const float* att2 = (const float*)d_in[20];
    const float* bias2= (const float*)d_in[21];
    const float* Wf1  = (const float*)d_in[22];
    const float* bf1  = (const float*)d_in[23];
    const float* Wf2  = (const float*)d_in[24];
    const float* bf2  = (const float*)d_in[25];

    cudaMemsetAsync(psum, 0, 2 * BBB * HIDD * sizeof(float));
    cudaMemsetAsync(pmax, 0, 2 * BBB * HIDD * sizeof(unsigned));
    cudaMemsetAsync(pcnt, 0, 2 * BBB * sizeof(int));

    dim3 ggrid(2, (n + 127) / 128);
    int eblocks = (E + 255) / 256;
    int nblocks_warp = (n + 7) / 8;   // 8 warps/block

    for (int g = 0; g < 2; g++) {
        const float* x     = (const float*)d_in[g * 4 + 0];
        const int*   ei    = (const int*)  d_in[g * 4 + 1];
        const float* ea    = (const float*)d_in[g * 4 + 2];
        const int*   batch = (const int*)  d_in[g * 4 + 3];
        const float* Wl  = g == 0 ? W1l : W1l;  // same weights for both graphs
        (void)Wl;

        // CSR build (reused by both layers)
        cudaMemsetAsync(deg, 0, n * sizeof(int));
        count_kernel<<<eblocks, 256>>>(ei, deg, E);
        scan_kernel<<<1, 1024>>>(deg, off, cur, n);
        scatter_kernel<<<eblocks, 256>>>(ei, ea, cur, src, eattr, E);

        // layer 1
        gemm_kernel<<<ggrid, 128>>>(x, W1l, b1l, xl, n);
        gemm_kernel<<<ggrid, 128>>>(x, W1r, b1r, xr, n);
        edge_kernel<<<nblocks_warp, 256>>>(xl, xr, eattr, src, off, W1e, att1, bias1, h, n);

        // layer 2
        gemm_kernel<<<ggrid, 128>>>(h, W2l, b2l, xl, n);
        gemm_kernel<<<ggrid, 128>>>(h, W2r, b2r, xr, n);
        edge_kernel<<<nblocks_warp, 256>>>(xl, xr, eattr, src, off, W2e, att2, bias2, h2, n);

        // pooling
        pool_kernel<<<200, 128>>>(h2, batch, psum + g * BBB * HIDD,
                                  pmax + g * BBB * HIDD, pcnt + g * BBB, n);
    }

    fc_kernel<<<1, 128>>>(psum, pmax, pcnt, Wf1, bf1, Wf2, bf2, (float*)d_out);
}

// round 2
// speedup vs baseline: 1.4094x; 1.4094x over previous
#include <cuda_runtime.h>
#include <math.h>

#define NN   50000
#define EE   800000
#define HIDD 128
#define FEE  16
#define BBB  8
#define NEG_SLOPE 0.2f

typedef unsigned long long u64;

// ---------------- scratch (static device memory; doubled for 2-stream overlap) ----
__device__ float g_xl[2][NN * HIDD];
__device__ float g_xr[2][NN * HIDD];
__device__ float g_h [2][NN * HIDD];
__device__ float g_h2[2][NN * HIDD];
__device__ int   g_deg[2][NN];
__device__ int   g_off[2][NN + 1];
__device__ int   g_cur[2][NN];
__device__ int   g_srcidx[2][EE];
__device__ float g_eattr[2][EE * FEE];
__device__ int   g_bsums[2][1024];
__device__ float    g_psum[2 * BBB * HIDD];
__device__ unsigned g_pmax[2 * BBB * HIDD];
__device__ int      g_pcnt[2 * BBB];

// ---------------- f32x2 packed helpers ----------------
__device__ __forceinline__ u64 pack2(float lo, float hi) {
    u64 r; asm("mov.b64 %0,{%1,%2};" : "=l"(r) : "f"(lo), "f"(hi)); return r;
}
__device__ __forceinline__ u64 splat2(float v) { return pack2(v, v); }
__device__ __forceinline__ u64 ffma2(u64 a, u64 b, u64 c) {
    u64 d; asm("fma.rn.f32x2 %0,%1,%2,%3;" : "=l"(d) : "l"(a), "l"(b), "l"(c)); return d;
}
__device__ __forceinline__ u64 fadd2(u64 a, u64 b) {
    u64 d; asm("add.rn.f32x2 %0,%1,%2;" : "=l"(d) : "l"(a), "l"(b)); return d;
}
__device__ __forceinline__ float2 unpack2(u64 v) {
    float2 f; asm("mov.b64 {%0,%1},%2;" : "=f"(f.x), "=f"(f.y) : "l"(v)); return f;
}

__device__ __forceinline__ unsigned enc_ord(float f) {
    unsigned u = __float_as_uint(f);
    return (u & 0x80000000u) ? ~u : (u | 0x80000000u);
}
__device__ __forceinline__ float dec_ord(unsigned e) {
    return (e & 0x80000000u) ? __uint_as_float(e ^ 0x80000000u) : __uint_as_float(~e);
}

// ---------------- CSR build ----------------
__global__ void count_kernel(const int* __restrict__ ei, int* __restrict__ deg, int E) {
    int e = blockIdx.x * blockDim.x + threadIdx.x;
    if (e >= E) return;
    atomicAdd(&deg[ei[E + e]], 1);
}

// 3-phase decoupled scan (block size 1024)
__global__ void partial_kernel(const int* __restrict__ deg, int* __restrict__ bsums, int n) {
    int tid = threadIdx.x;
    int i = blockIdx.x * 1024 + tid;
    int v = (i < n) ? deg[i] : 0;
#pragma unroll
    for (int o = 16; o; o >>= 1) v += __shfl_xor_sync(0xffffffffu, v, o);
    __shared__ int ws[32];
    if ((tid & 31) == 0) ws[tid >> 5] = v;
    __syncthreads();
    if (tid < 32) {
        int s = ws[tid];
#pragma unroll
        for (int o = 16; o; o >>= 1) s += __shfl_xor_sync(0xffffffffu, s, o);
        if (tid == 0) bsums[blockIdx.x] = s;
    }
}

__global__ void scan_bsums_kernel(int* __restrict__ bsums, int nb,
                                  int* __restrict__ off, int n) {
    int tid = threadIdx.x;
    int lane = tid & 31, wid = tid >> 5;
    int v = (tid < nb) ? bsums[tid] : 0;
    int x = v;
#pragma unroll
    for (int o = 1; o < 32; o <<= 1) {
        int t = __shfl_up_sync(0xffffffffu, x, o);
        if (lane >= o) x += t;
    }
    __shared__ int ws[32];
    if (lane == 31) ws[wid] = x;
    __syncthreads();
    if (wid == 0) {
        int s = ws[lane];
#pragma unroll
        for (int o = 1; o < 32; o <<= 1) {
            int t = __shfl_up_sync(0xffffffffu, s, o);
            if (lane >= o) s += t;
        }
        ws[lane] = s;
    }
    __syncthreads();
    int incl = (wid ? ws[wid - 1] : 0) + x;
    if (tid < nb) bsums[tid] = incl - v;       // exclusive
    if (tid == nb - 1) off[n] = incl;          // total = E
}

__global__ void write_off_kernel(const int* __restrict__ deg, const int* __restrict__ bscan,
                                 int* __restrict__ off, int* __restrict__ cur, int n) {
    int tid = threadIdx.x;
    int i = blockIdx.x * 1024 + tid;
    int lane = tid & 31, wid = tid >> 5;
    int v = (i < n) ? deg[i] : 0;
    int x = v;
#pragma unroll
    for (int o = 1; o < 32; o <<= 1) {
        int t = __shfl_up_sync(0xffffffffu, x, o);
        if (lane >= o) x += t;
    }
    __shared__ int ws[32];
    if (lane == 31) ws[wid] = x;
    __syncthreads();
    if (wid == 0) {
        int s = ws[lane];
#pragma unroll
        for (int o = 1; o < 32; o <<= 1) {
            int t = __shfl_up_sync(0xffffffffu, s, o);
            if (lane >= o) s += t;
        }
        ws[lane] = s;
    }
    __syncthreads();
    int excl = bscan[blockIdx.x] + (wid ? ws[wid - 1] : 0) + x - v;
    if (i < n) { off[i] = excl; cur[i] = excl; }
}

__global__ void scatter_kernel(const int* __restrict__ ei, const float* __restrict__ eattr_in,
                               int* __restrict__ cur, int* __restrict__ csr_src,
                               float* __restrict__ eattr_out, int E) {
    int e = blockIdx.x * blockDim.x + threadIdx.x;
    if (e >= E) return;
    int src = ei[e];
    int dst = ei[E + e];
    int pos = atomicAdd(&cur[dst], 1);
    csr_src[pos] = src;
    const float4* s = (const float4*)&eattr_in[(size_t)e * FEE];
    float4* d = (float4*)&eattr_out[(size_t)pos * FEE];
    d[0] = s[0]; d[1] = s[1]; d[2] = s[2]; d[3] = s[3];
}

// ---------------- fused dual node GEMM (Wl and Wr in one launch) ----------------
// grid (4, ceil(n/128)): blockIdx.x>>1 selects W, &1 selects col half. 128 threads.
__global__ __launch_bounds__(128) void gemm2_kernel(
    const float* __restrict__ A,
    const float* __restrict__ Wl, const float* __restrict__ bl, float* __restrict__ outl,
    const float* __restrict__ Wr, const float* __restrict__ br, float* __restrict__ outr,
    int nrows)
{
    __shared__ __align__(16) float As[2][16][132];
    __shared__ __align__(16) float Bs[2][16][64];
    int tid  = threadIdx.x;
    int which = blockIdx.x >> 1;
    const float* W    = which ? Wr : Wl;
    const float* bias = which ? br : bl;
    float*       out  = which ? outr : outl;
    int row0 = blockIdx.y * 128;
    int col0 = (blockIdx.x & 1) * 64;
    int tr = tid & 15;
    int tc = tid >> 4;

    u64 acc2[8][4];
#pragma unroll
    for (int i = 0; i < 8; i++)
#pragma unroll
        for (int j = 0; j < 4; j++) acc2[i][j] = 0ull;

    float4 aR[4], bR[2];

    // load tile k0 into regs
    auto load_tile = [&](int k0) {
#pragma unroll
        for (int i = 0; i < 4; i++) {
            int r = (tid >> 2) + 32 * i;
            int kq = (tid & 3) * 4;
            int grow = row0 + r;
            aR[i] = (grow < nrows) ? *(const float4*)&A[(size_t)grow * 128 + k0 + kq]
                                   : make_float4(0.f, 0.f, 0.f, 0.f);
        }
#pragma unroll
        for (int i = 0; i < 2; i++) {
            int t = tid + i * 128;
            int k = t >> 4;
            int cq = (t & 15) * 4;
            bR[i] = *(const float4*)&W[(size_t)(k0 + k) * 128 + col0 + cq];
        }
    };
    auto store_tile = [&](int buf) {
#pragma unroll
        for (int i = 0; i < 4; i++) {
            int r = (tid >> 2) + 32 * i;
            int kq = (tid & 3) * 4;
            As[buf][kq + 0][r] = aR[i].x; As[buf][kq + 1][r] = aR[i].y;
            As[buf][kq + 2][r] = aR[i].z; As[buf][kq + 3][r] = aR[i].w;
        }
#pragma unroll
        for (int i = 0; i < 2; i++) {
            int t = tid + i * 128;
            int k = t >> 4;
            int cq = (t & 15) * 4;
            *(float4*)&Bs[buf][k][cq] = bR[i];
        }
    };

    load_tile(0);
    store_tile(0);
    __syncthreads();

#pragma unroll
    for (int s = 0; s < 8; s++) {
        if (s < 7) load_tile((s + 1) * 16);
        int buf = s & 1;
#pragma unroll
        for (int k = 0; k < 16; k++) {
            float4 a0 = *(const float4*)&As[buf][k][tr * 4];
            float4 a1 = *(const float4*)&As[buf][k][64 + tr * 4];
            ulonglong2 b0 = *(const ulonglong2*)&Bs[buf][k][tc * 4];
            ulonglong2 b1 = *(const ulonglong2*)&Bs[buf][k][32 + tc * 4];
            u64 bb[4] = {b0.x, b0.y, b1.x, b1.y};
            float ar[8] = {a0.x, a0.y, a0.z, a0.w, a1.x, a1.y, a1.z, a1.w};
#pragma unroll
            for (int i = 0; i < 8; i++) {
                u64 ai = splat2(ar[i]);
#pragma unroll
                for (int j = 0; j < 4; j++) acc2[i][j] = ffma2(ai, bb[j], acc2[i][j]);
            }
        }
        if (s < 7) store_tile((s + 1) & 1);
        __syncthreads();
    }

    float4 bA = *(const float4*)&bias[col0 + tc * 4];
    float4 bB = *(const float4*)&bias[col0 + 32 + tc * 4];
#pragma unroll
    for (int i = 0; i < 8; i++) {
        int grow = row0 + ((i < 4) ? (tr * 4 + i) : (64 + tr * 4 + i - 4));
        if (grow >= nrows) continue;
        float2 c0 = unpack2(acc2[i][0]);
        float2 c1 = unpack2(acc2[i][1]);
        float2 c2 = unpack2(acc2[i][2]);
        float2 c3 = unpack2(acc2[i][3]);
        float4 o0 = make_float4(c0.x + bA.x, c0.y + bA.y, c1.x + bA.z, c1.y + bA.w);
        float4 o1 = make_float4(c2.x + bB.x, c2.y + bB.y, c3.x + bB.z, c3.y + bB.w);
        *(float4*)&out[(size_t)grow * 128 + col0 + tc * 4]      = o0;
        *(float4*)&out[(size_t)grow * 128 + col0 + 32 + tc * 4] = o1;
    }
}

// ---------------- fused GATv2 edge pass (one warp per destination node) ----------------
__global__ __launch_bounds__(128) void edge_kernel(
    const float* __restrict__ xl, const float* __restrict__ xr,
    const float* __restrict__ eattr, const int* __restrict__ csr_src,
    const int* __restrict__ off, const float* __restrict__ We,
    const float* __restrict__ att, const float* __restrict__ bias,
    float* __restrict__ out, int n_nodes)
{
    int warp = (blockIdx.x * blockDim.x + threadIdx.x) >> 5;
    int lane = threadIdx.x & 31;
    if (warp >= n_nodes) return;
    int ch = ((lane >> 3) << 5) + ((lane & 7) << 2);   // head = lane/8, 4 ch each

    u64 Wreg2[16][2];
#pragma unroll
    for (int k = 0; k < 16; k++) {
        ulonglong2 w = *(const ulonglong2*)&We[k * 128 + ch];
        Wreg2[k][0] = w.x; Wreg2[k][1] = w.y;
    }
    float4 att4 = *(const float4*)&att[ch];
    ulonglong2 xrp = *(const ulonglong2*)&xr[(size_t)warp * 128 + ch];

    u64 acc0 = 0ull, acc1 = 0ull;
    float denom = 0.f;
    int s = off[warp], e = off[warp + 1];

    for (int i = s; i < e; i++) {
        int src = __ldg(&csr_src[i]);
        ulonglong2 xlp = *(const ulonglong2*)&xl[(size_t)src * 128 + ch];
        u64 m0 = fadd2(xlp.x, xrp.x);
        u64 m1 = fadd2(xlp.y, xrp.y);
#pragma unroll
        for (int kk = 0; kk < 4; kk++) {
            float4 ea = *(const float4*)&eattr[(size_t)i * FEE + kk * 4];
            u64 e0 = splat2(ea.x), e1 = splat2(ea.y), e2 = splat2(ea.z), e3 = splat2(ea.w);
            m0 = ffma2(e0, Wreg2[4 * kk + 0][0], m0);
            m1 = ffma2(e0, Wreg2[4 * kk + 0][1], m1);
            m0 = ffma2(e1, Wreg2[4 * kk + 1][0], m0);
            m1 = ffma2(e1, Wreg2[4 * kk + 1][1], m1);
            m0 = ffma2(e2, Wreg2[4 * kk + 2][0], m0);
            m1 = ffma2(e2, Wreg2[4 * kk + 2][1], m1);
            m0 = ffma2(e3, Wreg2[4 * kk + 3][0], m0);
            m1 = ffma2(e3, Wreg2[4 * kk + 3][1], m1);
        }
        float2 f0 = unpack2(m0), f1 = unpack2(m1);
        // leaky_relu(x) = max(x, 0.2x)  (valid since 0 < slope < 1)
        float l0 = fmaxf(f0.x, NEG_SLOPE * f0.x);
        float l1 = fmaxf(f0.y, NEG_SLOPE * f0.y);
        float l2 = fmaxf(f1.x, NEG_SLOPE * f1.x);
        float l3 = fmaxf(f1.y, NEG_SLOPE * f1.y);
        float p = l0 * att4.x + l1 * att4.y + l2 * att4.z + l3 * att4.w;
        p += __shfl_xor_sync(0xffffffffu, p, 1);
        p += __shfl_xor_sync(0xffffffffu, p, 2);
        p += __shfl_xor_sync(0xffffffffu, p, 4);
        float ex = __expf(p);
        denom += ex;
        u64 exp2v = splat2(ex);
        acc0 = ffma2(exp2v, xlp.x, acc0);
        acc1 = ffma2(exp2v, xlp.y, acc1);
    }
    float inv = 1.f / (denom + 1e-16f);
    float4 b4 = *(const float4*)&bias[ch];
    float2 a0 = unpack2(acc0), a1 = unpack2(acc1);
    float ox = a0.x * inv + b4.x;
    float oy = a0.y * inv + b4.y;
    float oz = a1.x * inv + b4.z;
    float ow = a1.y * inv + b4.w;
    float4 o;
    o.x = (ox > 0.f) ? ox : expm1f(ox);
    o.y = (oy > 0.f) ? oy : expm1f(oy);
    o.z = (oz > 0.f) ? oz : expm1f(oz);
    o.w = (ow > 0.f) ? ow : expm1f(ow);
    *(float4*)&out[(size_t)warp * 128 + ch] = o;
}

// ---------------- batch pooling ----------------
__global__ __launch_bounds__(128) void pool_kernel(
    const float* __restrict__ h, const int* __restrict__ batch,
    float* __restrict__ gsum, unsigned* __restrict__ gmax, int* __restrict__ gcnt,
    int n_nodes)
{
    __shared__ float    ssum[BBB][HIDD];
    __shared__ unsigned smax[BBB][HIDD];
    __shared__ int      scnt[BBB];
    int tid = threadIdx.x;
#pragma unroll
    for (int b = 0; b < BBB; b++) { ssum[b][tid] = 0.f; smax[b][tid] = 0u; }
    if (tid < BBB) scnt[tid] = 0;
    __syncthreads();
    int chunk = (n_nodes + gridDim.x - 1) / gridDim.x;
    int st = blockIdx.x * chunk;
    int en = min(st + chunk, n_nodes);
    for (int n = st; n < en; n++) {
        int b = __ldg(&batch[n]);
        float v = h[(size_t)n * 128 + tid];
        ssum[b][tid] += v;
        unsigned ev = enc_ord(v);
        if (ev > smax[b][tid]) smax[b][tid] = ev;
        if (tid == 0) scnt[b]++;
    }
    __syncthreads();
#pragma unroll
    for (int b = 0; b < BBB; b++) {
        atomicAdd(&gsum[b * HIDD + tid], ssum[b][tid]);
        atomicMax(&gmax[b * HIDD + tid], smax[b][tid]);
    }
    if (tid < BBB) atomicAdd(&gcnt[tid], scnt[tid]);
}

// ---------------- FC head (one block per batch element) ----------------
__global__ __launch_bounds__(128) void fc_kernel(
    const float* __restrict__ gsum, const unsigned* __restrict__ gmax,
    const int* __restrict__ gcnt,
    const float* __restrict__ Wf1, const float* __restrict__ bf1,
    const float* __restrict__ Wf2, const float* __restrict__ bf2,
    float* __restrict__ out)
{
    __shared__ float comb[512];
    __shared__ float hid[128];
    int b = blockIdx.x;
    int tid = threadIdx.x;
#pragma unroll
    for (int g = 0; g < 2; g++) {
        int cnt = gcnt[g * BBB + b];
        float invc = 1.f / (float)max(cnt, 1);
        float mean = gsum[(size_t)(g * BBB + b) * HIDD + tid] * invc;
        unsigned mu = gmax[(size_t)(g * BBB + b) * HIDD + tid];
        float mx = (cnt > 0) ? dec_ord(mu) : 0.f;
        comb[g * 256 + tid]       = mean;
        comb[g * 256 + 128 + tid] = mx;
    }
    __syncthreads();
    float a = bf1[tid];
#pragma unroll 8
    for (int i = 0; i < 512; i++) a += comb[i] * Wf1[(size_t)i * 128 + tid];
    hid[tid] = fmaxf(a, 0.f);
    __syncthreads();
    if (tid < 32) {
        float s = 0.f;
        for (int j = tid; j < 128; j += 32) s += hid[j] * Wf2[j];
        s += __shfl_xor_sync(0xffffffffu, s, 1);
        s += __shfl_xor_sync(0xffffffffu, s, 2);
        s += __shfl_xor_sync(0xffffffffu, s, 4);
        s += __shfl_xor_sync(0xffffffffu, s, 8);
        s += __shfl_xor_sync(0xffffffffu, s, 16);
        if (tid == 0) out[b] = 1.f / (1.f + __expf(-(s + bf2[0])));
    }
}

// ---------------- launch ----------------
extern "C" void kernel_launch(void* const* d_in, const int* in_sizes, int n_in,
                              void* d_out, int out_size)
{
    (void)n_in; (void)out_size;
    int n = in_sizes[3];          // nodes
    int E = in_sizes[1] / 2;      // edges

    static cudaStream_t s2 = 0;
    static cudaEvent_t evF = 0, evJ = 0;
    if (!s2) {
        cudaStreamCreateWithFlags(&s2, cudaStreamNonBlocking);
        cudaEventCreateWithFlags(&evF, cudaEventDisableTiming);
        cudaEventCreateWithFlags(&evJ, cudaEventDisableTiming);
    }

    void* p;
    float *xl, *xr, *h, *h2, *eattr, *psum;
    int *deg, *off, *cur, *srcb, *pcnt, *bsums;
    unsigned *pmax;
    cudaGetSymbolAddress(&p, g_xl);     xl    = (float*)p;
    cudaGetSymbolAddress(&p, g_xr);     xr    = (float*)p;
    cudaGetSymbolAddress(&p, g_h);      h     = (float*)p;
    cudaGetSymbolAddress(&p, g_h2);     h2    = (float*)p;
    cudaGetSymbolAddress(&p, g_deg);    deg   = (int*)p;
    cudaGetSymbolAddress(&p, g_off);    off   = (int*)p;
    cudaGetSymbolAddress(&p, g_cur);    cur   = (int*)p;
    cudaGetSymbolAddress(&p, g_srcidx); srcb  = (int*)p;
    cudaGetSymbolAddress(&p, g_eattr);  eattr = (float*)p;
    cudaGetSymbolAddress(&p, g_bsums);  bsums = (int*)p;
    cudaGetSymbolAddress(&p, g_psum);   psum  = (float*)p;
    cudaGetSymbolAddress(&p, g_pmax);   pmax  = (unsigned*)p;
    cudaGetSymbolAddress(&p, g_pcnt);   pcnt  = (int*)p;

    const float* W1l  = (const float*)d_in[8];
    const float* b1l  = (const float*)d_in[9];
    const float* W1r  = (const float*)d_in[10];
    const float* b1r  = (const float*)d_in[11];
    const float* W1e  = (const float*)d_in[12];
    const float* att1 = (const float*)d_in[13];
    const float* bias1= (const float*)d_in[14];
    const float* W2l  = (const float*)d_in[15];
    const float* b2l  = (const float*)d_in[16];
    const float* W2r  = (const float*)d_in[17];
    const float* b2r  = (const float*)d_in[18];
    const float* W2e  = (const float*)d_in[19];
    const float* att2 = (const float*)d_in[20];
    const float* bias2= (const float*)d_in[21];
    const float* Wf1  = (const float*)d_in[22];
    const float* bf1  = (const float*)d_in[23];
    const float* Wf2  = (const float*)d_in[24];
    const float* bf2  = (const float*)d_in[25];

    cudaMemsetAsync(psum, 0, 2 * BBB * HIDD * sizeof(float), 0);
    cudaMemsetAsync(pmax, 0, 2 * BBB * HIDD * sizeof(unsigned), 0);
    cudaMemsetAsync(pcnt, 0, 2 * BBB * sizeof(int), 0);

    // fork: graph B pipeline waits on pool-buffer init, then runs on s2
    cudaEventRecord(evF, 0);
    cudaStreamWaitEvent(s2, evF, 0);

    dim3 ggrid(4, (n + 127) / 128);
    int eblocks = (E + 255) / 256;
    int nb1024 = (n + 1023) / 1024;
    int wblocks = (n * 32 + 127) / 128;

    for (int g = 0; g < 2; g++) {
        cudaStream_t st = (g == 0) ? (cudaStream_t)0 : s2;
        const float* x     = (const float*)d_in[g * 4 + 0];
        const int*   ei    = (const int*)  d_in[g * 4 + 1];
        const float* ea    = (const float*)d_in[g * 4 + 2];
        const int*   batch = (const int*)  d_in[g * 4 + 3];
        float* xl_g    = xl    + (size_t)g * NN * HIDD;
        float* xr_g    = xr    + (size_t)g * NN * HIDD;
        float* h_g     = h     + (size_t)g * NN * HIDD;
        float* h2_g    = h2    + (size_t)g * NN * HIDD;
        int*   deg_g   = deg   + (size_t)g * NN;
        int*   off_g   = off   + (size_t)g * (NN + 1);
        int*   cur_g   = cur   + (size_t)g * NN;
        int*   src_g   = srcb  + (size_t)g * EE;
        float* eattr_g = eattr + (size_t)g * EE * FEE;
        int*   bs_g    = bsums + (size_t)g * 1024;

        // CSR build
        cudaMemsetAsync(deg_g, 0, n * sizeof(int), st);
        count_kernel<<<eblocks, 256, 0, st>>>(ei, deg_g, E);
        partial_kernel<<<nb1024, 1024, 0, st>>>(deg_g, bs_g, n);
        scan_bsums_kernel<<<1, 1024, 0, st>>>(bs_g, nb1024, off_g, n);
        write_off_kernel<<<nb1024, 1024, 0, st>>>(deg_g, bs_g, off_g, cur_g, n);
        scatter_kernel<<<eblocks, 256, 0, st>>>(ei, ea, cur_g, src_g, eattr_g, E);

        // layer 1
        gemm2_kernel<<<ggrid, 128, 0, st>>>(x, W1l, b1l, xl_g, W1r, b1r, xr_g, n);
        edge_kernel<<<wblocks, 128, 0, st>>>(xl_g, xr_g, eattr_g, src_g, off_g,
                                             W1e, att1, bias1, h_g, n);
        // layer 2
        gemm2_kernel<<<ggrid, 128, 0, st>>>(h_g, W2l, b2l, xl_g, W2r, b2r, xr_g, n);
        edge_kernel<<<wblocks, 128, 0, st>>>(xl_g, xr_g, eattr_g, src_g, off_g,
                                             W2e, att2, bias2, h2_g, n);
        // pooling
        pool_kernel<<<200, 128, 0, st>>>(h2_g, batch, psum + g * BBB * HIDD,
                                         pmax + g * BBB * HIDD, pcnt + g * BBB, n);
    }

    // join
    cudaEventRecord(evJ, s2);
    cudaStreamWaitEvent((cudaStream_t)0, evJ, 0);

    fc_kernel<<<BBB, 128>>>(psum, pmax, pcnt, Wf1, bf1, Wf2, bf2, (float*)d_out);
}

// round 3
// speedup vs baseline: 1.6768x; 1.1897x over previous
#include <cuda_runtime.h>
#include <math.h>

#define NN   50000
#define EE   800000
#define HIDD 128
#define FEE  16
#define BBB  8
#define NEG_SLOPE 0.2f

typedef unsigned long long u64;

// ---------------- scratch (static device memory; doubled for 2-stream overlap) ----
__device__ float g_xl[2][NN * HIDD];
__device__ float g_xr[2][NN * HIDD];
__device__ float g_h [2][NN * HIDD];
__device__ float g_h2[2][NN * HIDD];
__device__ int   g_deg[2][NN];
__device__ int   g_off[2][NN + 1];
__device__ int   g_cur[2][NN];
__device__ int   g_srcidx[2][EE];
__device__ float g_eattr[2][EE * FEE];
__device__ int   g_bsums[2][1024];
__device__ float    g_psum[2 * BBB * HIDD];
__device__ unsigned g_pmax[2 * BBB * HIDD];
__device__ int      g_pcnt[2 * BBB];

// ---------------- f32x2 packed helpers ----------------
__device__ __forceinline__ u64 pack2(float lo, float hi) {
    u64 r; asm("mov.b64 %0,{%1,%2};" : "=l"(r) : "f"(lo), "f"(hi)); return r;
}
__device__ __forceinline__ u64 splat2(float v) { return pack2(v, v); }
__device__ __forceinline__ u64 ffma2(u64 a, u64 b, u64 c) {
    u64 d; asm("fma.rn.f32x2 %0,%1,%2,%3;" : "=l"(d) : "l"(a), "l"(b), "l"(c)); return d;
}
__device__ __forceinline__ u64 fadd2(u64 a, u64 b) {
    u64 d; asm("add.rn.f32x2 %0,%1,%2;" : "=l"(d) : "l"(a), "l"(b)); return d;
}
__device__ __forceinline__ float2 unpack2(u64 v) {
    float2 f; asm("mov.b64 {%0,%1},%2;" : "=f"(f.x), "=f"(f.y) : "l"(v)); return f;
}

__device__ __forceinline__ unsigned enc_ord(float f) {
    unsigned u = __float_as_uint(f);
    return (u & 0x80000000u) ? ~u : (u | 0x80000000u);
}
__device__ __forceinline__ float dec_ord(unsigned e) {
    return (e & 0x80000000u) ? __uint_as_float(e ^ 0x80000000u) : __uint_as_float(~e);
}

// ---------------- CSR build ----------------
__global__ void count_kernel(const int* __restrict__ ei, int* __restrict__ deg, int E) {
    int e = blockIdx.x * blockDim.x + threadIdx.x;
    if (e >= E) return;
    atomicAdd(&deg[ei[E + e]], 1);
}

__global__ void partial_kernel(const int* __restrict__ deg, int* __restrict__ bsums, int n) {
    int tid = threadIdx.x;
    int i = blockIdx.x * 1024 + tid;
    int v = (i < n) ? deg[i] : 0;
#pragma unroll
    for (int o = 16; o; o >>= 1) v += __shfl_xor_sync(0xffffffffu, v, o);
    __shared__ int ws[32];
    if ((tid & 31) == 0) ws[tid >> 5] = v;
    __syncthreads();
    if (tid < 32) {
        int s = ws[tid];
#pragma unroll
        for (int o = 16; o; o >>= 1) s += __shfl_xor_sync(0xffffffffu, s, o);
        if (tid == 0) bsums[blockIdx.x] = s;
    }
}

__global__ void scan_bsums_kernel(int* __restrict__ bsums, int nb,
                                  int* __restrict__ off, int n) {
    int tid = threadIdx.x;
    int lane = tid & 31, wid = tid >> 5;
    int v = (tid < nb) ? bsums[tid] : 0;
    int x = v;
#pragma unroll
    for (int o = 1; o < 32; o <<= 1) {
        int t = __shfl_up_sync(0xffffffffu, x, o);
        if (lane >= o) x += t;
    }
    __shared__ int ws[32];
    if (lane == 31) ws[wid] = x;
    __syncthreads();
    if (wid == 0) {
        int s = ws[lane];
#pragma unroll
        for (int o = 1; o < 32; o <<= 1) {
            int t = __shfl_up_sync(0xffffffffu, s, o);
            if (lane >= o) s += t;
        }
        ws[lane] = s;
    }
    __syncthreads();
    int incl = (wid ? ws[wid - 1] : 0) + x;
    if (tid < nb) bsums[tid] = incl - v;
    if (tid == nb - 1) off[n] = incl;
}

__global__ void write_off_kernel(const int* __restrict__ deg, const int* __restrict__ bscan,
                                 int* __restrict__ off, int* __restrict__ cur, int n) {
    int tid = threadIdx.x;
    int i = blockIdx.x * 1024 + tid;
    int lane = tid & 31, wid = tid >> 5;
    int v = (i < n) ? deg[i] : 0;
    int x = v;
#pragma unroll
    for (int o = 1; o < 32; o <<= 1) {
        int t = __shfl_up_sync(0xffffffffu, x, o);
        if (lane >= o) x += t;
    }
    __shared__ int ws[32];
    if (lane == 31) ws[wid] = x;
    __syncthreads();
    if (wid == 0) {
        int s = ws[lane];
#pragma unroll
        for (int o = 1; o < 32; o <<= 1) {
            int t = __shfl_up_sync(0xffffffffu, s, o);
            if (lane >= o) s += t;
        }
        ws[lane] = s;
    }
    __syncthreads();
    int excl = bscan[blockIdx.x] + (wid ? ws[wid - 1] : 0) + x - v;
    if (i < n) { off[i] = excl; cur[i] = excl; }
}

__global__ void scatter_kernel(const int* __restrict__ ei, const float* __restrict__ eattr_in,
                               int* __restrict__ cur, int* __restrict__ csr_src,
                               float* __restrict__ eattr_out, int E) {
    int e = blockIdx.x * blockDim.x + threadIdx.x;
    if (e >= E) return;
    int src = ei[e];
    int dst = ei[E + e];
    int pos = atomicAdd(&cur[dst], 1);
    csr_src[pos] = src;
    const float4* s = (const float4*)&eattr_in[(size_t)e * FEE];
    float4* d = (float4*)&eattr_out[(size_t)pos * FEE];
    d[0] = s[0]; d[1] = s[1]; d[2] = s[2]; d[3] = s[3];
}

// ---------------- fused dual node GEMM (Wl and Wr in one launch) ----------------
__global__ __launch_bounds__(128) void gemm2_kernel(
    const float* __restrict__ A,
    const float* __restrict__ Wl, const float* __restrict__ bl, float* __restrict__ outl,
    const float* __restrict__ Wr, const float* __restrict__ br, float* __restrict__ outr,
    int nrows)
{
    __shared__ __align__(16) float As[2][16][132];
    __shared__ __align__(16) float Bs[2][16][64];
    int tid  = threadIdx.x;
    int which = blockIdx.x >> 1;
    const float* W    = which ? Wr : Wl;
    const float* bias = which ? br : bl;
    float*       out  = which ? outr : outl;
    int row0 = blockIdx.y * 128;
    int col0 = (blockIdx.x & 1) * 64;
    int tr = tid & 15;
    int tc = tid >> 4;

    u64 acc2[8][4];
#pragma unroll
    for (int i = 0; i < 8; i++)
#pragma unroll
        for (int j = 0; j < 4; j++) acc2[i][j] = 0ull;

    float4 aR[4], bR[2];

    auto load_tile = [&](int k0) {
#pragma unroll
        for (int i = 0; i < 4; i++) {
            int r = (tid >> 2) + 32 * i;
            int kq = (tid & 3) * 4;
            int grow = row0 + r;
            aR[i] = (grow < nrows) ? *(const float4*)&A[(size_t)grow * 128 + k0 + kq]
                                   : make_float4(0.f, 0.f, 0.f, 0.f);
        }
#pragma unroll
        for (int i = 0; i < 2; i++) {
            int t = tid + i * 128;
            int k = t >> 4;
            int cq = (t & 15) * 4;
            bR[i] = *(const float4*)&W[(size_t)(k0 + k) * 128 + col0 + cq];
        }
    };
    auto store_tile = [&](int buf) {
#pragma unroll
        for (int i = 0; i < 4; i++) {
            int r = (tid >> 2) + 32 * i;
            int kq = (tid & 3) * 4;
            As[buf][kq + 0][r] = aR[i].x; As[buf][kq + 1][r] = aR[i].y;
            As[buf][kq + 2][r] = aR[i].z; As[buf][kq + 3][r] = aR[i].w;
        }
#pragma unroll
        for (int i = 0; i < 2; i++) {
            int t = tid + i * 128;
            int k = t >> 4;
            int cq = (t & 15) * 4;
            *(float4*)&Bs[buf][k][cq] = bR[i];
        }
    };

    load_tile(0);
    store_tile(0);
    __syncthreads();

#pragma unroll
    for (int s = 0; s < 8; s++) {
        if (s < 7) load_tile((s + 1) * 16);
        int buf = s & 1;
#pragma unroll
        for (int k = 0; k < 16; k++) {
            float4 a0 = *(const float4*)&As[buf][k][tr * 4];
            float4 a1 = *(const float4*)&As[buf][k][64 + tr * 4];
            ulonglong2 b0 = *(const ulonglong2*)&Bs[buf][k][tc * 4];
            ulonglong2 b1 = *(const ulonglong2*)&Bs[buf][k][32 + tc * 4];
            u64 bb[4] = {b0.x, b0.y, b1.x, b1.y};
            float ar[8] = {a0.x, a0.y, a0.z, a0.w, a1.x, a1.y, a1.z, a1.w};
#pragma unroll
            for (int i = 0; i < 8; i++) {
                u64 ai = splat2(ar[i]);
#pragma unroll
                for (int j = 0; j < 4; j++) acc2[i][j] = ffma2(ai, bb[j], acc2[i][j]);
            }
        }
        if (s < 7) store_tile((s + 1) & 1);
        __syncthreads();
    }

    float4 bA = *(const float4*)&bias[col0 + tc * 4];
    float4 bB = *(const float4*)&bias[col0 + 32 + tc * 4];
#pragma unroll
    for (int i = 0; i < 8; i++) {
        int grow = row0 + ((i < 4) ? (tr * 4 + i) : (64 + tr * 4 + i - 4));
        if (grow >= nrows) continue;
        float2 c0 = unpack2(acc2[i][0]);
        float2 c1 = unpack2(acc2[i][1]);
        float2 c2 = unpack2(acc2[i][2]);
        float2 c3 = unpack2(acc2[i][3]);
        float4 o0 = make_float4(c0.x + bA.x, c0.y + bA.y, c1.x + bA.z, c1.y + bA.w);
        float4 o1 = make_float4(c2.x + bB.x, c2.y + bB.y, c3.x + bB.z, c3.y + bB.w);
        *(float4*)&out[(size_t)grow * 128 + col0 + tc * 4]      = o0;
        *(float4*)&out[(size_t)grow * 128 + col0 + 32 + tc * 4] = o1;
    }
}

// ---------------- fused GATv2 edge pass ----------------
// One warp per destination node; W_e in shared memory (conflict-free LDS.128);
// manual unroll-by-2 with independent chains for latency hiding.
__global__ __launch_bounds__(256) void edge_kernel(
    const float* __restrict__ xl, const float* __restrict__ xr,
    const float* __restrict__ eattr, const int* __restrict__ csr_src,
    const int* __restrict__ off, const float* __restrict__ We,
    const float* __restrict__ att, const float* __restrict__ bias,
    float* __restrict__ out, int n_nodes)
{
    __shared__ __align__(16) float sWe[16][128];   // 8 KB
    for (int i = threadIdx.x; i < 16 * 128 / 4; i += 256)
        *(float4*)&sWe[0][i * 4] = *(const float4*)&We[i * 4];
    __syncthreads();

    int warp = (blockIdx.x * blockDim.x + threadIdx.x) >> 5;
    int lane = threadIdx.x & 31;
    if (warp >= n_nodes) return;
    int ch = ((lane >> 3) << 5) + ((lane & 7) << 2);   // head = lane/8, 4 ch each

    float4 att4 = *(const float4*)&att[ch];
    ulonglong2 xrp = *(const ulonglong2*)&xr[(size_t)warp * 128 + ch];

    u64 acc0 = 0ull, acc1 = 0ull;
    float denom = 0.f;
    int s = off[warp], e = off[warp + 1];
    int i = s;

    for (; i + 1 < e; i += 2) {
        int s0 = __ldg(&csr_src[i]);
        int s1 = __ldg(&csr_src[i + 1]);
        ulonglong2 xA = *(const ulonglong2*)&xl[(size_t)s0 * 128 + ch];
        ulonglong2 xB = *(const ulonglong2*)&xl[(size_t)s1 * 128 + ch];
        float4 eA[4], eB[4];
#pragma unroll
        for (int kk = 0; kk < 4; kk++) {
            eA[kk] = *(const float4*)&eattr[(size_t)i * FEE + kk * 4];
            eB[kk] = *(const float4*)&eattr[(size_t)(i + 1) * FEE + kk * 4];
        }
        u64 mA0 = fadd2(xA.x, xrp.x), mA1 = fadd2(xA.y, xrp.y);
        u64 mB0 = fadd2(xB.x, xrp.x), mB1 = fadd2(xB.y, xrp.y);
#pragma unroll
        for (int kk = 0; kk < 4; kk++) {
            float es[8] = {eA[kk].x, eA[kk].y, eA[kk].z, eA[kk].w,
                           eB[kk].x, eB[kk].y, eB[kk].z, eB[kk].w};
#pragma unroll
            for (int r = 0; r < 4; r++) {
                ulonglong2 w = *(const ulonglong2*)&sWe[4 * kk + r][ch];
                u64 sa = splat2(es[r]);
                u64 sb = splat2(es[4 + r]);
                mA0 = ffma2(sa, w.x, mA0);
                mA1 = ffma2(sa, w.y, mA1);
                mB0 = ffma2(sb, w.x, mB0);
                mB1 = ffma2(sb, w.y, mB1);
            }
        }
        float2 fA0 = unpack2(mA0), fA1 = unpack2(mA1);
        float2 fB0 = unpack2(mB0), fB1 = unpack2(mB1);
        float pA = fmaxf(fA0.x, NEG_SLOPE * fA0.x) * att4.x
                 + fmaxf(fA0.y, NEG_SLOPE * fA0.y) * att4.y
                 + fmaxf(fA1.x, NEG_SLOPE * fA1.x) * att4.z
                 + fmaxf(fA1.y, NEG_SLOPE * fA1.y) * att4.w;
        float pB = fmaxf(fB0.x, NEG_SLOPE * fB0.x) * att4.x
                 + fmaxf(fB0.y, NEG_SLOPE * fB0.y) * att4.y
                 + fmaxf(fB1.x, NEG_SLOPE * fB1.x) * att4.z
                 + fmaxf(fB1.y, NEG_SLOPE * fB1.y) * att4.w;
        pA += __shfl_xor_sync(0xffffffffu, pA, 1);
        pB += __shfl_xor_sync(0xffffffffu, pB, 1);
        pA += __shfl_xor_sync(0xffffffffu, pA, 2);
        pB += __shfl_xor_sync(0xffffffffu, pB, 2);
        pA += __shfl_xor_sync(0xffffffffu, pA, 4);
        pB += __shfl_xor_sync(0xffffffffu, pB, 4);
        float exA = __expf(pA);
        float exB = __expf(pB);
        denom += exA + exB;
        u64 eA2 = splat2(exA), eB2 = splat2(exB);
        acc0 = ffma2(eA2, xA.x, acc0);
        acc1 = ffma2(eA2, xA.y, acc1);
        acc0 = ffma2(eB2, xB.x, acc0);
        acc1 = ffma2(eB2, xB.y, acc1);
    }
    if (i < e) {
        int s0 = __ldg(&csr_src[i]);
        ulonglong2 xA = *(const ulonglong2*)&xl[(size_t)s0 * 128 + ch];
        u64 mA0 = fadd2(xA.x, xrp.x), mA1 = fadd2(xA.y, xrp.y);
#pragma unroll
        for (int kk = 0; kk < 4; kk++) {
            float4 ea = *(const float4*)&eattr[(size_t)i * FEE + kk * 4];
            float es[4] = {ea.x, ea.y, ea.z, ea.w};
#pragma unroll
            for (int r = 0; r < 4; r++) {
                ulonglong2 w = *(const ulonglong2*)&sWe[4 * kk + r][ch];
                u64 sa = splat2(es[r]);
                mA0 = ffma2(sa, w.x, mA0);
                mA1 = ffma2(sa, w.y, mA1);
            }
        }
        float2 fA0 = unpack2(mA0), fA1 = unpack2(mA1);
        float pA = fmaxf(fA0.x, NEG_SLOPE * fA0.x) * att4.x
                 + fmaxf(fA0.y, NEG_SLOPE * fA0.y) * att4.y
                 + fmaxf(fA1.x, NEG_SLOPE * fA1.x) * att4.z
                 + fmaxf(fA1.y, NEG_SLOPE * fA1.y) * att4.w;
        pA += __shfl_xor_sync(0xffffffffu, pA, 1);
        pA += __shfl_xor_sync(0xffffffffu, pA, 2);
        pA += __shfl_xor_sync(0xffffffffu, pA, 4);
        float exA = __expf(pA);
        denom += exA;
        u64 eA2 = splat2(exA);
        acc0 = ffma2(eA2, xA.x, acc0);
        acc1 = ffma2(eA2, xA.y, acc1);
    }

    float inv = 1.f / (denom + 1e-16f);
    float4 b4 = *(const float4*)&bias[ch];
    float2 a0 = unpack2(acc0), a1 = unpack2(acc1);
    float ox = a0.x * inv + b4.x;
    float oy = a0.y * inv + b4.y;
    float oz = a1.x * inv + b4.z;
    float ow = a1.y * inv + b4.w;
    float4 o;
    o.x = (ox > 0.f) ? ox : expm1f(ox);
    o.y = (oy > 0.f) ? oy : expm1f(oy);
    o.z = (oz > 0.f) ? oz : expm1f(oz);
    o.w = (ow > 0.f) ? ow : expm1f(ow);
    *(float4*)&out[(size_t)warp * 128 + ch] = o;
}

// ---------------- batch pooling ----------------
__global__ __launch_bounds__(128) void pool_kernel(
    const float* __restrict__ h, const int* __restrict__ batch,
    float* __restrict__ gsum, unsigned* __restrict__ gmax, int* __restrict__ gcnt,
    int n_nodes)
{
    __shared__ float    ssum[BBB][HIDD];
    __shared__ unsigned smax[BBB][HIDD];
    __shared__ int      scnt[BBB];
    int tid = threadIdx.x;
#pragma unroll
    for (int b = 0; b < BBB; b++) { ssum[b][tid] = 0.f; smax[b][tid] = 0u; }
    if (tid < BBB) scnt[tid] = 0;
    __syncthreads();
    int chunk = (n_nodes + gridDim.x - 1) / gridDim.x;
    int st = blockIdx.x * chunk;
    int en = min(st + chunk, n_nodes);
    for (int n = st; n < en; n++) {
        int b = __ldg(&batch[n]);
        float v = h[(size_t)n * 128 + tid];
        ssum[b][tid] += v;
        unsigned ev = enc_ord(v);
        if (ev > smax[b][tid]) smax[b][tid] = ev;
        if (tid == 0) scnt[b]++;
    }
    __syncthreads();
#pragma unroll
    for (int b = 0; b < BBB; b++) {
        atomicAdd(&gsum[b * HIDD + tid], ssum[b][tid]);
        atomicMax(&gmax[b * HIDD + tid], smax[b][tid]);
    }
    if (tid < BBB) atomicAdd(&gcnt[tid], scnt[tid]);
}

// ---------------- FC head ----------------
__global__ __launch_bounds__(128) void fc_kernel(
    const float* __restrict__ gsum, const unsigned* __restrict__ gmax,
    const int* __restrict__ gcnt,
    const float* __restrict__ Wf1, const float* __restrict__ bf1,
    const float* __restrict__ Wf2, const float* __restrict__ bf2,
    float* __restrict__ out)
{
    __shared__ float comb[512];
    __shared__ float hid[128];
    int b = blockIdx.x;
    int tid = threadIdx.x;
#pragma unroll
    for (int g = 0; g < 2; g++) {
        int cnt = gcnt[g * BBB + b];
        float invc = 1.f / (float)max(cnt, 1);
        float mean = gsum[(size_t)(g * BBB + b) * HIDD + tid] * invc;
        unsigned mu = gmax[(size_t)(g * BBB + b) * HIDD + tid];
        float mx = (cnt > 0) ? dec_ord(mu) : 0.f;
        comb[g * 256 + tid]       = mean;
        comb[g * 256 + 128 + tid] = mx;
    }
    __syncthreads();
    float a = bf1[tid];
#pragma unroll 8
    for (int i = 0; i < 512; i++) a += comb[i] * Wf1[(size_t)i * 128 + tid];
    hid[tid] = fmaxf(a, 0.f);
    __syncthreads();
    if (tid < 32) {
        float s = 0.f;
        for (int j = tid; j < 128; j += 32) s += hid[j] * Wf2[j];
        s += __shfl_xor_sync(0xffffffffu, s, 1);
        s += __shfl_xor_sync(0xffffffffu, s, 2);
        s += __shfl_xor_sync(0xffffffffu, s, 4);
        s += __shfl_xor_sync(0xffffffffu, s, 8);
        s += __shfl_xor_sync(0xffffffffu, s, 16);
        if (tid == 0) out[b] = 1.f / (1.f + __expf(-(s + bf2[0])));
    }
}

// ---------------- launch ----------------
extern "C" void kernel_launch(void* const* d_in, const int* in_sizes, int n_in,
                              void* d_out, int out_size)
{
    (void)n_in; (void)out_size;
    int n = in_sizes[3];
    int E = in_sizes[1] / 2;

    static cudaStream_t s2 = 0;
    static cudaEvent_t evF = 0, evJ = 0;
    if (!s2) {
        cudaStreamCreateWithFlags(&s2, cudaStreamNonBlocking);
        cudaEventCreateWithFlags(&evF, cudaEventDisableTiming);
        cudaEventCreateWithFlags(&evJ, cudaEventDisableTiming);
    }

    void* p;
    float *xl, *xr, *h, *h2, *eattr, *psum;
    int *deg, *off, *cur, *srcb, *pcnt, *bsums;
    unsigned *pmax;
    cudaGetSymbolAddress(&p, g_xl);     xl    = (float*)p;
    cudaGetSymbolAddress(&p, g_xr);     xr    = (float*)p;
    cudaGetSymbolAddress(&p, g_h);      h     = (float*)p;
    cudaGetSymbolAddress(&p, g_h2);     h2    = (float*)p;
    cudaGetSymbolAddress(&p, g_deg);    deg   = (int*)p;
    cudaGetSymbolAddress(&p, g_off);    off   = (int*)p;
    cudaGetSymbolAddress(&p, g_cur);    cur   = (int*)p;
    cudaGetSymbolAddress(&p, g_srcidx); srcb  = (int*)p;
    cudaGetSymbolAddress(&p, g_eattr);  eattr = (float*)p;
    cudaGetSymbolAddress(&p, g_bsums);  bsums = (int*)p;
    cudaGetSymbolAddress(&p, g_psum);   psum  = (float*)p;
    cudaGetSymbolAddress(&p, g_pmax);   pmax  = (unsigned*)p;
    cudaGetSymbolAddress(&p, g_pcnt);   pcnt  = (int*)p;

    const float* W1l  = (const float*)d_in[8];
    const float* b1l  = (const float*)d_in[9];
    const float* W1r  = (const float*)d_in[10];
    const float* b1r  = (const float*)d_in[11];
    const float* W1e  = (const float*)d_in[12];
    const float* att1 = (const float*)d_in[13];
    const float* bias1= (const float*)d_in[14];
    const float* W2l  = (const float*)d_in[15];
    const float* b2l  = (const float*)d_in[16];
    const float* W2r  = (const float*)d_in[17];
    const float* b2r  = (const float*)d_in[18];
    const float* W2e  = (const float*)d_in[19];
    const float* att2 = (const float*)d_in[20];
    const float* bias2= (const float*)d_in[21];
    const float* Wf1  = (const float*)d_in[22];
    const float* bf1  = (const float*)d_in[23];
    const float* Wf2  = (const float*)d_in[24];
    const float* bf2  = (const float*)d_in[25];

    cudaMemsetAsync(psum, 0, 2 * BBB * HIDD * sizeof(float), 0);
    cudaMemsetAsync(pmax, 0, 2 * BBB * HIDD * sizeof(unsigned), 0);
    cudaMemsetAsync(pcnt, 0, 2 * BBB * sizeof(int), 0);

    cudaEventRecord(evF, 0);
    cudaStreamWaitEvent(s2, evF, 0);

    dim3 ggrid(4, (n + 127) / 128);
    int eblocks = (E + 255) / 256;
    int nb1024 = (n + 1023) / 1024;
    int wblocks = (n + 7) / 8;   // 8 warps per 256-thread block

    for (int g = 0; g < 2; g++) {
        cudaStream_t st = (g == 0) ? (cudaStream_t)0 : s2;
        const float* x     = (const float*)d_in[g * 4 + 0];
        const int*   ei    = (const int*)  d_in[g * 4 + 1];
        const float* ea    = (const float*)d_in[g * 4 + 2];
        const int*   batch = (const int*)  d_in[g * 4 + 3];
        float* xl_g    = xl    + (size_t)g * NN * HIDD;
        float* xr_g    = xr    + (size_t)g * NN * HIDD;
        float* h_g     = h     + (size_t)g * NN * HIDD;
        float* h2_g    = h2    + (size_t)g * NN * HIDD;
        int*   deg_g   = deg   + (size_t)g * NN;
        int*   off_g   = off   + (size_t)g * (NN + 1);
        int*   cur_g   = cur   + (size_t)g * NN;
        int*   src_g   = srcb  + (size_t)g * EE;
        float* eattr_g = eattr + (size_t)g * EE * FEE;
        int*   bs_g    = bsums + (size_t)g * 1024;

        cudaMemsetAsync(deg_g, 0, n * sizeof(int), st);
        count_kernel<<<eblocks, 256, 0, st>>>(ei, deg_g, E);
        partial_kernel<<<nb1024, 1024, 0, st>>>(deg_g, bs_g, n);
        scan_bsums_kernel<<<1, 1024, 0, st>>>(bs_g, nb1024, off_g, n);
        write_off_kernel<<<nb1024, 1024, 0, st>>>(deg_g, bs_g, off_g, cur_g, n);
        scatter_kernel<<<eblocks, 256, 0, st>>>(ei, ea, cur_g, src_g, eattr_g, E);

        gemm2_kernel<<<ggrid, 128, 0, st>>>(x, W1l, b1l, xl_g, W1r, b1r, xr_g, n);
        edge_kernel<<<wblocks, 256, 0, st>>>(xl_g, xr_g, eattr_g, src_g, off_g,
                                             W1e, att1, bias1, h_g, n);
        gemm2_kernel<<<ggrid, 128, 0, st>>>(h_g, W2l, b2l, xl_g, W2r, b2r, xr_g, n);
        edge_kernel<<<wblocks, 256, 0, st>>>(xl_g, xr_g, eattr_g, src_g, off_g,
                                             W2e, att2, bias2, h2_g, n);
        pool_kernel<<<200, 128, 0, st>>>(h2_g, batch, psum + g * BBB * HIDD,
                                         pmax + g * BBB * HIDD, pcnt + g * BBB, n);
    }

    cudaEventRecord(evJ, s2);
    cudaStreamWaitEvent((cudaStream_t)0, evJ, 0);

    fc_kernel<<<BBB, 128>>>(psum, pmax, pcnt, Wf1, bf1, Wf2, bf2, (float*)d_out);
}